// round 15
// baseline (speedup 1.0000x reference)
#include <cuda_runtime.h>
#include <cuda_bf16.h>
#include <math.h>
#include <stdint.h>

#define BB 4096
#define SS 128
#define DD 64
#define HH 256
#define INF 8192
#define H4 1024
#define KSPLIT 8
#define NGRP 32
#define GRP_CTAS 8
#define BNZ 16

// ---------------- scratch (device globals; zero-init at load) ----------------
__device__ float g_scale[INF];
__device__ float g_shift[INF];
__device__ float g_bns[BNZ * INF];
__device__ float g_bns2[BNZ * INF];
__device__ __nv_bfloat16 g_xnh[(size_t)BB * INF];
__device__ __nv_bfloat16 g_xnl[(size_t)BB * INF];
__device__ __nv_bfloat16 g_wh[(size_t)INF * INF];
__device__ __nv_bfloat16 g_wl[(size_t)INF * INF];
__device__ __nv_bfloat16 g_pjh[(size_t)BB * INF];
__device__ __nv_bfloat16 g_pjl[(size_t)BB * INF];
__device__ __nv_bfloat16 g_whhh[(size_t)H4 * HH];        // permuted W_hh hi
__device__ __nv_bfloat16 g_whhl[(size_t)H4 * HH];
__device__ __nv_bfloat16 g_wihh[(size_t)H4 * DD];        // permuted W_ih hi
__device__ __nv_bfloat16 g_wihl[(size_t)H4 * DD];
__device__ float g_biasp[H4];
__device__ __nv_bfloat16 g_wtah[(size_t)SS * SS * HH];
__device__ __nv_bfloat16 g_wtal[(size_t)SS * SS * HH];
__device__ __nv_bfloat16 g_hsbh[(size_t)BB * SS * HH];
__device__ __nv_bfloat16 g_hsbl[(size_t)BB * SS * HH];
__device__ float g_pattn[(size_t)KSPLIT * BB * SS];
__device__ float g_beta[(size_t)BB * SS];
__device__ unsigned g_barv[NGRP * 32];   // per-group barrier counters (padded)

// ============================ PTX helpers (family-wide) ============================
__device__ __forceinline__ uint32_t smem_to_u32(const void* p) {
    uint32_t a;
    asm("{ .reg .u64 t; cvta.to.shared.u64 t, %1; cvt.u32.u64 %0, t; }" : "=r"(a) : "l"(p));
    return a;
}
__device__ __forceinline__ void ldsm_x4(uint32_t* r, uint32_t a) {
    asm volatile("ldmatrix.sync.aligned.m8n8.x4.shared.b16 {%0,%1,%2,%3}, [%4];"
                 : "=r"(r[0]), "=r"(r[1]), "=r"(r[2]), "=r"(r[3]) : "r"(a));
}
__device__ __forceinline__ void ldsm_x2(uint32_t* r, uint32_t a) {
    asm volatile("ldmatrix.sync.aligned.m8n8.x2.shared.b16 {%0,%1}, [%2];"
                 : "=r"(r[0]), "=r"(r[1]) : "r"(a));
}
__device__ __forceinline__ void mma16816(float* c, const uint32_t* a, const uint32_t* b) {
    asm volatile(
        "mma.sync.aligned.m16n8k16.row.col.f32.bf16.bf16.f32 "
        "{%0,%1,%2,%3}, {%4,%5,%6,%7}, {%8,%9}, {%0,%1,%2,%3};"
        : "+f"(c[0]), "+f"(c[1]), "+f"(c[2]), "+f"(c[3])
        : "r"(a[0]), "r"(a[1]), "r"(a[2]), "r"(a[3]), "r"(b[0]), "r"(b[1]));
}
__device__ __forceinline__ void cp_async16(uint32_t saddr, const void* gptr) {
    asm volatile("cp.async.cg.shared.global [%0], [%1], 16;" :: "r"(saddr), "l"(gptr));
}
#define CP_COMMIT() asm volatile("cp.async.commit_group;" ::: "memory")
#define CP_WAIT1()  asm volatile("cp.async.wait_group 1;" ::: "memory")
#define CP_WAIT0()  asm volatile("cp.async.wait_group 0;" ::: "memory")

#define TILE_B (128 * 80)
#define STAGE_B (4 * TILE_B)
#define SMEM_MMA (2 * STAGE_B)           // 81920 B (proj/attn)
#define SMEM_SCAN (2 * STAGE_B + 16384)  // 98304 B (+ persistent c tile)

// ---------------- BatchNorm stats: two-phase ----------------
__global__ void bn_stats_part(const float* __restrict__ x) {
    int k = blockIdx.x * blockDim.x + threadIdx.x;
    int z = blockIdx.y;
    float s = 0.f, s2 = 0.f;
    #pragma unroll 8
    for (int b = z * (BB / BNZ); b < (z + 1) * (BB / BNZ); b++) {
        float v = x[(size_t)b * INF + k];
        s += v; s2 += v * v;
    }
    g_bns[z * INF + k] = s;
    g_bns2[z * INF + k] = s2;
}

__global__ void bn_finalize(const float* __restrict__ gamma,
                            const float* __restrict__ beta) {
    int k = blockIdx.x * blockDim.x + threadIdx.x;
    float s = 0.f, s2 = 0.f;
    #pragma unroll
    for (int z = 0; z < BNZ; z++) {
        s += g_bns[z * INF + k];
        s2 += g_bns2[z * INF + k];
    }
    float mean = s * (1.f / BB);
    float var = s2 * (1.f / BB) - mean * mean;
    float sc = gamma[k] * rsqrtf(var + 1e-5f);
    g_scale[k] = sc;
    g_shift[k] = beta[k] - mean * sc;
}

// BN apply fused with bf16 hi/lo split
__global__ void bn_apply_split(const float* __restrict__ x) {
    size_t i = (size_t)blockIdx.x * blockDim.x + threadIdx.x;
    float4 v = ((const float4*)x)[i];
    int k = (int)((i * 4) & (INF - 1));
    float o0 = fmaf(v.x, g_scale[k + 0], g_shift[k + 0]);
    float o1 = fmaf(v.y, g_scale[k + 1], g_shift[k + 1]);
    float o2 = fmaf(v.z, g_scale[k + 2], g_shift[k + 2]);
    float o3 = fmaf(v.w, g_scale[k + 3], g_shift[k + 3]);
    __nv_bfloat16 h0 = __float2bfloat16(o0), h1 = __float2bfloat16(o1);
    __nv_bfloat16 h2 = __float2bfloat16(o2), h3 = __float2bfloat16(o3);
    __nv_bfloat162 ph0; ph0.x = h0; ph0.y = h1;
    __nv_bfloat162 ph1; ph1.x = h2; ph1.y = h3;
    *(__nv_bfloat162*)(g_xnh + i * 4) = ph0;
    *(__nv_bfloat162*)(g_xnh + i * 4 + 2) = ph1;
    __nv_bfloat162 pl0, pl1;
    pl0.x = __float2bfloat16(o0 - __bfloat162float(h0));
    pl0.y = __float2bfloat16(o1 - __bfloat162float(h1));
    pl1.x = __float2bfloat16(o2 - __bfloat162float(h2));
    pl1.y = __float2bfloat16(o3 - __bfloat162float(h3));
    *(__nv_bfloat162*)(g_xnl + i * 4) = pl0;
    *(__nv_bfloat162*)(g_xnl + i * 4 + 2) = pl1;
}

// generic fp32 -> bf16 hi/lo split
__global__ void cvt_split(const float* __restrict__ src,
                          __nv_bfloat16* __restrict__ dh,
                          __nv_bfloat16* __restrict__ dl) {
    size_t i = (size_t)blockIdx.x * blockDim.x + threadIdx.x;
    float4 v = ((const float4*)src)[i];
    __nv_bfloat16 h0 = __float2bfloat16(v.x), h1 = __float2bfloat16(v.y);
    __nv_bfloat16 h2 = __float2bfloat16(v.z), h3 = __float2bfloat16(v.w);
    __nv_bfloat162 ph0; ph0.x = h0; ph0.y = h1;
    __nv_bfloat162 ph1; ph1.x = h2; ph1.y = h3;
    *(__nv_bfloat162*)(dh + i * 4) = ph0;
    *(__nv_bfloat162*)(dh + i * 4 + 2) = ph1;
    __nv_bfloat162 pl0, pl1;
    pl0.x = __float2bfloat16(v.x - __bfloat162float(h0));
    pl0.y = __float2bfloat16(v.y - __bfloat162float(h1));
    pl1.x = __float2bfloat16(v.z - __bfloat162float(h2));
    pl1.y = __float2bfloat16(v.w - __bfloat162float(h3));
    *(__nv_bfloat162*)(dl + i * 4) = pl0;
    *(__nv_bfloat162*)(dl + i * 4 + 2) = pl1;
}

// Blocked permutation (validated) + per-group barrier reset.
__global__ void prep_perm(const float* __restrict__ Whh, const float* __restrict__ Wih,
                          const float* __restrict__ b_ih, const float* __restrict__ b_hh) {
    int r = blockIdx.x;
    if (r == 0 && threadIdx.x < NGRP) g_barv[threadIdx.x * 32] = 0u;
    int t = r >> 7, j = r & 127;
    int orig = (j >> 5) * 256 + t * 32 + (j & 31);
    for (int k = threadIdx.x; k < HH; k += blockDim.x) {
        float v = Whh[(size_t)orig * HH + k];
        __nv_bfloat16 h = __float2bfloat16(v);
        g_whhh[(size_t)r * HH + k] = h;
        g_whhl[(size_t)r * HH + k] = __float2bfloat16(v - __bfloat162float(h));
    }
    for (int k = threadIdx.x; k < DD; k += blockDim.x) {
        float v = Wih[(size_t)orig * DD + k];
        __nv_bfloat16 h = __float2bfloat16(v);
        g_wihh[(size_t)r * DD + k] = h;
        g_wihl[(size_t)r * DD + k] = __float2bfloat16(v - __bfloat162float(h));
    }
    if (threadIdx.x == 0) g_biasp[r] = b_ih[orig] + b_hh[orig];
}

// ============ proj = xn @ W_in^T via mma.sync bf16x3 -> bf16 hi/lo out ============
__global__ void __launch_bounds__(256, 2)
proj_mma() {
    extern __shared__ __align__(128) char sm[];
    const int tid = threadIdx.x;
    const int wid = tid >> 5, lane = tid & 31;
    const int m0 = blockIdx.x * 128;
    const int n0 = blockIdx.y * 128;
    const int wm = (wid >> 2) * 64;
    const int wn = (wid & 3) * 32;
    const uint32_t smu = smem_to_u32(sm);

    const __nv_bfloat16* src0 = g_xnh + (size_t)m0 * INF;
    const __nv_bfloat16* src1 = g_xnl + (size_t)m0 * INF;
    const __nv_bfloat16* src2 = g_wh + (size_t)n0 * INF;
    const __nv_bfloat16* src3 = g_wl + (size_t)n0 * INF;

    float acc[4][4][4];
    #pragma unroll
    for (int i = 0; i < 4; i++)
        #pragma unroll
        for (int j = 0; j < 4; j++)
            #pragma unroll
            for (int f = 0; f < 4; f++) acc[i][j][f] = 0.f;

    const int r0 = tid >> 2, g0 = tid & 3;
    const int r1 = (tid + 256) >> 2;

    auto stage = [&](int st, int k0) {
        uint32_t sb = smu + st * STAGE_B;
        const __nv_bfloat16* s[4] = {src0, src1, src2, src3};
        #pragma unroll
        for (int t = 0; t < 4; t++) {
            cp_async16(sb + t * TILE_B + r0 * 80 + g0 * 16,
                       s[t] + (size_t)r0 * INF + k0 + g0 * 8);
            cp_async16(sb + t * TILE_B + r1 * 80 + g0 * 16,
                       s[t] + (size_t)r1 * INF + k0 + g0 * 8);
        }
        CP_COMMIT();
    };
    auto compute = [&](int st) {
        const uint32_t sAh = smu + st * STAGE_B;
        const uint32_t sAl = sAh + TILE_B;
        const uint32_t sBh = sAh + 2 * TILE_B;
        const uint32_t sBl = sAh + 3 * TILE_B;
        #pragma unroll
        for (int ks = 0; ks < 2; ks++) {
            const int kb = ks * 32;
            uint32_t bh[4][2], bl[4][2];
            const uint32_t boff = (uint32_t)(wn + (lane & 7)) * 80 + kb + ((lane >> 3) & 1) * 16;
            #pragma unroll
            for (int ni = 0; ni < 4; ni++) {
                ldsm_x2(bh[ni], sBh + boff + ni * 8 * 80);
                ldsm_x2(bl[ni], sBl + boff + ni * 8 * 80);
            }
            const uint32_t aoff = (uint32_t)(wm + (lane & 15)) * 80 + kb + (lane >> 4) * 16;
            #pragma unroll
            for (int mi = 0; mi < 4; mi++) {
                uint32_t ah[4], al[4];
                ldsm_x4(ah, sAh + aoff + mi * 16 * 80);
                ldsm_x4(al, sAl + aoff + mi * 16 * 80);
                #pragma unroll
                for (int ni = 0; ni < 4; ni++) {
                    mma16816(acc[mi][ni], ah, bh[ni]);
                    mma16816(acc[mi][ni], ah, bl[ni]);
                    mma16816(acc[mi][ni], al, bh[ni]);
                }
            }
        }
    };

    stage(0, 0);
    int cur = 0;
    #pragma unroll 1
    for (int k0 = 0; k0 < INF; k0 += 32) {
        bool more = (k0 + 32 < INF);
        if (more) stage(cur ^ 1, k0 + 32);
        if (more) CP_WAIT1(); else CP_WAIT0();
        __syncthreads();
        compute(cur);
        __syncthreads();
        cur ^= 1;
    }

    const int gid = lane >> 2, tig = lane & 3;
    #pragma unroll
    for (int mi = 0; mi < 4; mi++) {
        int row0 = m0 + wm + mi * 16 + gid;
        #pragma unroll
        for (int ni = 0; ni < 4; ni++) {
            int col = n0 + wn + ni * 8 + tig * 2;
            const float* a = acc[mi][ni];
            #pragma unroll
            for (int half = 0; half < 2; half++) {
                int row = row0 + half * 8;
                float c0 = a[half * 2 + 0], c1 = a[half * 2 + 1];
                __nv_bfloat162 hp, lp;
                hp.x = __float2bfloat16(c0); hp.y = __float2bfloat16(c1);
                lp.x = __float2bfloat16(c0 - __bfloat162float(hp.x));
                lp.y = __float2bfloat16(c1 - __bfloat162float(hp.y));
                *(__nv_bfloat162*)(g_pjh + (size_t)row * INF + col) = hp;
                *(__nv_bfloat162*)(g_pjl + (size_t)row * INF + col) = lp;
            }
        }
    }
}

// ===== persistent scan: ih-first chunk order + cross-barrier ih prefetch =====
__device__ __forceinline__ float fsig(float x) {
    return __fdividef(1.f, 1.f + __expf(-x));
}
__device__ __forceinline__ float ftanh(float x) {
    return __fdividef(2.f, 1.f + __expf(-2.f * x)) - 1.f;
}

__global__ void __launch_bounds__(256, 2)
scan_persist() {
    extern __shared__ __align__(128) char sm[];
    const int tid = threadIdx.x;
    const int wid = tid >> 5, lane = tid & 31;
    const int m0 = blockIdx.x * 128;
    const int t = blockIdx.y;          // h-quarter
    const int n0 = t * 128;
    const int wm = (wid >> 2) * 64;
    const int wn = (wid & 3) * 32;
    const uint32_t smu = smem_to_u32(sm);
    const size_t ld1 = (size_t)SS * HH;
    const int r0 = tid >> 2, g0 = tid & 3;
    const int r1 = (tid + 256) >> 2;
    const int gid = lane >> 2, tig = lane & 3;
    unsigned* barp = &g_barv[blockIdx.x * 32];
    float* c_sm = (float*)(sm + 2 * STAGE_B);  // persistent 4096-float c tile

    // chunk i of step ss: i<2 -> ih chunk (independent of hs), i>=2 -> hh chunk
    auto stage = [&](int st, int chunk, int ss) {
        const __nv_bfloat16 *pah, *pal, *pbh, *pbl;
        size_t la; int lb, k0;
        if (chunk < 2) {
            k0 = chunk * 32;
            pah = g_pjh + (size_t)ss * DD; pal = g_pjl + (size_t)ss * DD; la = INF;
            pbh = g_wihh; pbl = g_wihl; lb = DD;
        } else {
            k0 = (chunk - 2) * 32;
            pah = g_hsbh + (size_t)(ss - 1) * HH; pal = g_hsbl + (size_t)(ss - 1) * HH;
            la = ld1;
            pbh = g_whhh; pbl = g_whhl; lb = HH;
        }
        uint32_t sb = smu + st * STAGE_B;
        cp_async16(sb + r0 * 80 + g0 * 16, pah + (size_t)(m0 + r0) * la + k0 + g0 * 8);
        cp_async16(sb + r1 * 80 + g0 * 16, pah + (size_t)(m0 + r1) * la + k0 + g0 * 8);
        cp_async16(sb + TILE_B + r0 * 80 + g0 * 16, pal + (size_t)(m0 + r0) * la + k0 + g0 * 8);
        cp_async16(sb + TILE_B + r1 * 80 + g0 * 16, pal + (size_t)(m0 + r1) * la + k0 + g0 * 8);
        cp_async16(sb + 2 * TILE_B + r0 * 80 + g0 * 16, pbh + (size_t)(n0 + r0) * lb + k0 + g0 * 8);
        cp_async16(sb + 2 * TILE_B + r1 * 80 + g0 * 16, pbh + (size_t)(n0 + r1) * lb + k0 + g0 * 8);
        cp_async16(sb + 3 * TILE_B + r0 * 80 + g0 * 16, pbl + (size_t)(n0 + r0) * lb + k0 + g0 * 8);
        cp_async16(sb + 3 * TILE_B + r1 * 80 + g0 * 16, pbl + (size_t)(n0 + r1) * lb + k0 + g0 * 8);
        CP_COMMIT();
    };

    // prologue: prefetch step 0's two ih chunks
    stage(0, 0, 0);
    stage(1, 1, 0);

    #pragma unroll 1
    for (int s = 0; s < SS; s++) {
        const int nq = (s == 0) ? 2 : 10;   // step 0: h_{-1}==0, hh chunks skipped

        float acc[4][4][4];
        #pragma unroll
        for (int i = 0; i < 4; i++)
            #pragma unroll
            for (int j = 0; j < 4; j++)
                #pragma unroll
                for (int f = 0; f < 4; f++) acc[i][j][f] = 0.f;

        auto compute = [&](int st) {
            const uint32_t sAh = smu + st * STAGE_B;
            const uint32_t sAl = sAh + TILE_B;
            const uint32_t sBh = sAh + 2 * TILE_B;
            const uint32_t sBl = sAh + 3 * TILE_B;
            #pragma unroll
            for (int ks = 0; ks < 2; ks++) {
                const int kb = ks * 32;
                uint32_t bh[4][2], bl[4][2];
                const uint32_t boff = (uint32_t)(wn + (lane & 7)) * 80 + kb + ((lane >> 3) & 1) * 16;
                #pragma unroll
                for (int ni = 0; ni < 4; ni++) {
                    ldsm_x2(bh[ni], sBh + boff + ni * 8 * 80);
                    ldsm_x2(bl[ni], sBl + boff + ni * 8 * 80);
                }
                const uint32_t aoff = (uint32_t)(wm + (lane & 15)) * 80 + kb + (lane >> 4) * 16;
                #pragma unroll
                for (int mi = 0; mi < 4; mi++) {
                    uint32_t ah[4], al[4];
                    ldsm_x4(ah, sAh + aoff + mi * 16 * 80);
                    ldsm_x4(al, sAl + aoff + mi * 16 * 80);
                    #pragma unroll
                    for (int ni = 0; ni < 4; ni++) {
                        mma16816(acc[mi][ni], ah, bh[ni]);
                        mma16816(acc[mi][ni], ah, bl[ni]);
                        mma16816(acc[mi][ni], al, bh[ni]);
                    }
                }
            }
        };

        // chunks [ih0, ih1, hh0..hh7]; ih0/ih1 already staged (prologue or prefetch)
        #pragma unroll 1
        for (int i = 0; i < nq; ++i) {
            if (i + 1 < nq) CP_WAIT1(); else CP_WAIT0();
            __syncthreads();
            compute(i & 1);
            __syncthreads();
            if (i + 2 < nq) stage(i & 1, i + 2, s);
        }

        // gate exchange via smem (MMA buffers dead; c_sm untouched)
        float* gsm = (float*)sm;       // 128 x 132 fp32
        #pragma unroll
        for (int mi = 0; mi < 4; mi++) {
            int row0 = wm + mi * 16 + gid;
            #pragma unroll
            for (int ni = 0; ni < 4; ni++) {
                int col = wn + ni * 8 + tig * 2;
                const float* a = acc[mi][ni];
                gsm[row0 * 132 + col] = a[0];
                gsm[row0 * 132 + col + 1] = a[1];
                gsm[(row0 + 8) * 132 + col] = a[2];
                gsm[(row0 + 8) * 132 + col + 1] = a[3];
            }
        }
        __syncthreads();

        // fused cell: 4096 cells, 16/thread, MUFU fast math; c in persistent smem
        #pragma unroll
        for (int u = 0; u < 16; u++) {
            int idx = tid + u * 256;
            int row = idx >> 5;
            int hq = idx & 31;
            float gi = gsm[row * 132 + hq]      + g_biasp[t * 128 + hq];
            float gf = gsm[row * 132 + 32 + hq] + g_biasp[t * 128 + 32 + hq];
            float gg = gsm[row * 132 + 64 + hq] + g_biasp[t * 128 + 64 + hq];
            float go = gsm[row * 132 + 96 + hq] + g_biasp[t * 128 + 96 + hq];
            float ig = fsig(gi);
            float fg = fsig(gf);
            float gv = ftanh(gg);
            float og = fsig(go);
            float cp = (s == 0) ? 0.f : c_sm[idx];
            float cn = fmaf(fg, cp, ig * gv);
            c_sm[idx] = cn;
            float hv = og * ftanh(cn);
            int b = m0 + row;
            int h = t * 32 + hq;
            size_t hidx = ((size_t)b * SS + s) * HH + h;
            __nv_bfloat16 hhi = __float2bfloat16(hv);
            g_hsbh[hidx] = hhi;
            g_hsbl[hidx] = __float2bfloat16(hv - __bfloat162float(hhi));
        }
        __syncthreads();

        if (s < SS - 1) {
            // prefetch next step's ih chunks (independent of hs) BEFORE the barrier
            stage(0, 0, s + 1);
            stage(1, 1, s + 1);
            // per-group barrier: only this m-block's 8 h-quarter CTAs sync
            if (tid == 0) {
                __threadfence();
                atomicAdd(barp, 1u);
                unsigned target = (unsigned)GRP_CTAS * (unsigned)(s + 1);
                while (atomicAdd(barp, 0u) < target) __nanosleep(32);
                __threadfence();
            }
            __syncthreads();
        }
    }
}

// ============ attention logits: split-K bf16x3 MMA -> fp32 partials ============
__global__ void __launch_bounds__(256, 2)
attn_mma() {
    extern __shared__ __align__(128) char sm[];
    const int tid = threadIdx.x;
    const int wid = tid >> 5, lane = tid & 31;
    const int m0 = blockIdx.y * 128;
    const int z = blockIdx.z;
    const int wm = (wid >> 2) * 64;
    const int wn = (wid & 3) * 32;
    const uint32_t smu = smem_to_u32(sm);
    const size_t ldk = (size_t)SS * HH;

    const __nv_bfloat16* src0 = g_hsbh + (size_t)m0 * ldk + z * 4096;
    const __nv_bfloat16* src1 = g_hsbl + (size_t)m0 * ldk + z * 4096;
    const __nv_bfloat16* src2 = g_wtah + z * 4096;
    const __nv_bfloat16* src3 = g_wtal + z * 4096;

    float acc[4][4][4];
    #pragma unroll
    for (int i = 0; i < 4; i++)
        #pragma unroll
        for (int j = 0; j < 4; j++)
            #pragma unroll
            for (int f = 0; f < 4; f++) acc[i][j][f] = 0.f;

    const int r0 = tid >> 2, g0 = tid & 3;
    const int r1 = (tid + 256) >> 2;

    auto stage = [&](int st, int k0) {
        uint32_t sb = smu + st * STAGE_B;
        cp_async16(sb + r0 * 80 + g0 * 16, src0 + (size_t)r0 * ldk + k0 + g0 * 8);
        cp_async16(sb + r1 * 80 + g0 * 16, src0 + (size_t)r1 * ldk + k0 + g0 * 8);
        cp_async16(sb + TILE_B + r0 * 80 + g0 * 16, src1 + (size_t)r0 * ldk + k0 + g0 * 8);
        cp_async16(sb + TILE_B + r1 * 80 + g0 * 16, src1 + (size_t)r1 * ldk + k0 + g0 * 8);
        cp_async16(sb + 2 * TILE_B + r0 * 80 + g0 * 16, src2 + (size_t)r0 * ldk + k0 + g0 * 8);
        cp_async16(sb + 2 * TILE_B + r1 * 80 + g0 * 16, src2 + (size_t)r1 * ldk + k0 + g0 * 8);
        cp_async16(sb + 3 * TILE_B + r0 * 80 + g0 * 16, src3 + (size_t)r0 * ldk + k0 + g0 * 8);
        cp_async16(sb + 3 * TILE_B + r1 * 80 + g0 * 16, src3 + (size_t)r1 * ldk + k0 + g0 * 8);
        CP_COMMIT();
    };
    auto compute = [&](int st) {
        const uint32_t sAh = smu + st * STAGE_B;
        const uint32_t sAl = sAh + TILE_B;
        const uint32_t sBh = sAh + 2 * TILE_B;
        const uint32_t sBl = sAh + 3 * TILE_B;
        #pragma unroll
        for (int ks = 0; ks < 2; ks++) {
            const int kb = ks * 32;
            uint32_t bh[4][2], bl[4][2];
            const uint32_t boff = (uint32_t)(wn + (lane & 7)) * 80 + kb + ((lane >> 3) & 1) * 16;
            #pragma unroll
            for (int ni = 0; ni < 4; ni++) {
                ldsm_x2(bh[ni], sBh + boff + ni * 8 * 80);
                ldsm_x2(bl[ni], sBl + boff + ni * 8 * 80);
            }
            const uint32_t aoff = (uint32_t)(wm + (lane & 15)) * 80 + kb + (lane >> 4) * 16;
            #pragma unroll
            for (int mi = 0; mi < 4; mi++) {
                uint32_t ah[4], al[4];
                ldsm_x4(ah, sAh + aoff + mi * 16 * 80);
                ldsm_x4(al, sAl + aoff + mi * 16 * 80);
                #pragma unroll
                for (int ni = 0; ni < 4; ni++) {
                    mma16816(acc[mi][ni], ah, bh[ni]);
                    mma16816(acc[mi][ni], ah, bl[ni]);
                    mma16816(acc[mi][ni], al, bh[ni]);
                }
            }
        }
    };

    stage(0, 0);
    int cur = 0;
    #pragma unroll 1
    for (int k0 = 0; k0 < 4096; k0 += 32) {
        bool more = (k0 + 32 < 4096);
        if (more) stage(cur ^ 1, k0 + 32);
        if (more) CP_WAIT1(); else CP_WAIT0();
        __syncthreads();
        compute(cur);
        __syncthreads();
        cur ^= 1;
    }

    const int gid = lane >> 2, tig = lane & 3;
    float* outp = g_pattn + (size_t)z * BB * SS;
    #pragma unroll
    for (int mi = 0; mi < 4; mi++) {
        int row0 = m0 + wm + mi * 16 + gid;
        #pragma unroll
        for (int ni = 0; ni < 4; ni++) {
            int col = wn + ni * 8 + tig * 2;
            float2 v0; v0.x = acc[mi][ni][0]; v0.y = acc[mi][ni][1];
            float2 v1; v1.x = acc[mi][ni][2]; v1.y = acc[mi][ni][3];
            *(float2*)(outp + (size_t)row0 * SS + col) = v0;
            *(float2*)(outp + (size_t)(row0 + 8) * SS + col) = v1;
        }
    }
}

// ---------------- attention: reduce split-K partials, relu, softmax ----------------
__global__ void attn_reduce_softmax(const float* __restrict__ b_ta) {
    int b = blockIdx.x;
    int t = threadIdx.x;  // 128
    __shared__ float sh[4];
    float v = 0.f;
    #pragma unroll
    for (int z = 0; z < KSPLIT; z++) v += g_pattn[((size_t)z * BB + b) * SS + t];
    v = fmaxf(v + b_ta[t], 0.f);
    float m = v;
    #pragma unroll
    for (int o = 16; o > 0; o >>= 1) m = fmaxf(m, __shfl_xor_sync(0xffffffffu, m, o));
    if ((t & 31) == 0) sh[t >> 5] = m;
    __syncthreads();
    float m4 = fmaxf(fmaxf(sh[0], sh[1]), fmaxf(sh[2], sh[3]));
    float e = expf(v - m4);
    float ssum = e;
    #pragma unroll
    for (int o = 16; o > 0; o >>= 1) ssum += __shfl_xor_sync(0xffffffffu, ssum, o);
    __syncthreads();
    if ((t & 31) == 0) sh[t >> 5] = ssum;
    __syncthreads();
    float tot = sh[0] + sh[1] + sh[2] + sh[3];
    g_beta[(size_t)b * SS + t] = e / tot;
}

// ---------------- pooled = sum_s beta*hs ; out = pooled @ W_out^T ----------------
__global__ void pool_out(const float* __restrict__ W_out, float* __restrict__ out) {
    int b = blockIdx.x;
    int t = threadIdx.x;  // 256, t == h
    __shared__ float sb[SS];
    __shared__ float red[8];
    if (t < SS) sb[t] = g_beta[(size_t)b * SS + t];
    __syncthreads();
    const __nv_bfloat16* hh = g_hsbh + (size_t)b * SS * HH + t;
    const __nv_bfloat16* hl = g_hsbl + (size_t)b * SS * HH + t;
    float acc = 0.f;
    #pragma unroll 4
    for (int s = 0; s < SS; s++) {
        float hv = __bfloat162float(hh[(size_t)s * HH]) + __bfloat162float(hl[(size_t)s * HH]);
        acc = fmaf(hv, sb[s], acc);
    }
    float v = acc * W_out[t];
    #pragma unroll
    for (int o = 16; o > 0; o >>= 1) v += __shfl_xor_sync(0xffffffffu, v, o);
    if ((t & 31) == 0) red[t >> 5] = v;
    __syncthreads();
    if (t == 0) {
        float r = 0.f;
        #pragma unroll
        for (int w = 0; w < 8; w++) r += red[w];
        out[b] = r;
    }
}

// ---------------- launch ----------------
extern "C" void kernel_launch(void* const* d_in, const int* in_sizes, int n_in,
                              void* d_out, int out_size) {
    const float* x     = (const float*)d_in[0];
    const float* gamma = (const float*)d_in[1];
    const float* beta  = (const float*)d_in[2];
    const float* W_in  = (const float*)d_in[3];
    const float* W_ih  = (const float*)d_in[4];
    const float* b_ih  = (const float*)d_in[5];
    const float* W_hh  = (const float*)d_in[6];
    const float* b_hh  = (const float*)d_in[7];
    const float* W_ta  = (const float*)d_in[8];
    const float* b_ta  = (const float*)d_in[9];
    const float* W_out = (const float*)d_in[10];
    float* out = (float*)d_out;

    __nv_bfloat16 *p_wh, *p_wl, *p_wtah, *p_wtal;
    cudaGetSymbolAddress((void**)&p_wh, g_wh);
    cudaGetSymbolAddress((void**)&p_wl, g_wl);
    cudaGetSymbolAddress((void**)&p_wtah, g_wtah);
    cudaGetSymbolAddress((void**)&p_wtal, g_wtal);

    cudaFuncSetAttribute(proj_mma, cudaFuncAttributeMaxDynamicSharedMemorySize, SMEM_MMA);
    cudaFuncSetAttribute(scan_persist, cudaFuncAttributeMaxDynamicSharedMemorySize, SMEM_SCAN);
    cudaFuncSetAttribute(attn_mma, cudaFuncAttributeMaxDynamicSharedMemorySize, SMEM_MMA);

    // BatchNorm (two-phase) + splits (+ blocked permutation; resets barriers)
    bn_stats_part<<<dim3(INF / 256, BNZ), 256>>>(x);
    bn_finalize<<<INF / 256, 256>>>(gamma, beta);
    bn_apply_split<<<(BB * INF / 4) / 256, 256>>>(x);
    cvt_split<<<((size_t)INF * INF / 4) / 256, 256>>>(W_in, p_wh, p_wl);
    cvt_split<<<((size_t)SS * SS * HH / 4) / 256, 256>>>(W_ta, p_wtah, p_wtal);
    prep_perm<<<H4, 256>>>(W_hh, W_ih, b_ih, b_hh);

    // proj = xn @ W_in^T -> bf16 hi/lo
    proj_mma<<<dim3(BB / 128, INF / 128), 256, SMEM_MMA>>>();

    // LSTM scan: persistent, per-group barriers, ih prefetch across barrier
    scan_persist<<<dim3(BB / 128, H4 / 128), 256, SMEM_SCAN>>>();

    // attention: split-K bf16 logits, fused reduce+relu+softmax, pool
    attn_mma<<<dim3(1, BB / 128, KSPLIT), 256, SMEM_MMA>>>();
    attn_reduce_softmax<<<BB, SS>>>(b_ta);
    pool_out<<<BB, HH>>>(W_out, out);
}

// round 16
// speedup vs baseline: 1.0202x; 1.0202x over previous
#include <cuda_runtime.h>
#include <cuda_bf16.h>
#include <math.h>
#include <stdint.h>

#define BB 4096
#define SS 128
#define DD 64
#define HH 256
#define INF 8192
#define H4 1024
#define KSPLIT 8
#define NGRP 32
#define GRP_CTAS 8
#define BNZ 16

// ---------------- scratch (device globals; zero-init at load) ----------------
__device__ float g_scale[INF];
__device__ float g_shift[INF];
__device__ float g_bns[BNZ * INF];
__device__ float g_bns2[BNZ * INF];
__device__ __nv_bfloat16 g_xnh[(size_t)BB * INF];
__device__ __nv_bfloat16 g_xnl[(size_t)BB * INF];
__device__ __nv_bfloat16 g_wh[(size_t)INF * INF];
__device__ __nv_bfloat16 g_wl[(size_t)INF * INF];
__device__ __nv_bfloat16 g_pjh[(size_t)BB * INF];
__device__ __nv_bfloat16 g_pjl[(size_t)BB * INF];
__device__ __nv_bfloat16 g_whhh[(size_t)H4 * HH];        // permuted W_hh hi
__device__ __nv_bfloat16 g_whhl[(size_t)H4 * HH];
__device__ __nv_bfloat16 g_wihh[(size_t)H4 * DD];        // permuted W_ih hi
__device__ __nv_bfloat16 g_wihl[(size_t)H4 * DD];
__device__ float g_biasp[H4];
__device__ __nv_bfloat16 g_wtah[(size_t)SS * SS * HH];
__device__ __nv_bfloat16 g_wtal[(size_t)SS * SS * HH];
__device__ __nv_bfloat16 g_hsbh[(size_t)BB * SS * HH];
__device__ __nv_bfloat16 g_hsbl[(size_t)BB * SS * HH];
__device__ float g_pattn[(size_t)KSPLIT * BB * SS];
__device__ float g_beta[(size_t)BB * SS];
__device__ unsigned g_barv[NGRP * 32];   // per-group barrier counters (padded)

// ============================ PTX helpers (family-wide) ============================
__device__ __forceinline__ uint32_t smem_to_u32(const void* p) {
    uint32_t a;
    asm("{ .reg .u64 t; cvta.to.shared.u64 t, %1; cvt.u32.u64 %0, t; }" : "=r"(a) : "l"(p));
    return a;
}
__device__ __forceinline__ void ldsm_x4(uint32_t* r, uint32_t a) {
    asm volatile("ldmatrix.sync.aligned.m8n8.x4.shared.b16 {%0,%1,%2,%3}, [%4];"
                 : "=r"(r[0]), "=r"(r[1]), "=r"(r[2]), "=r"(r[3]) : "r"(a));
}
__device__ __forceinline__ void ldsm_x2(uint32_t* r, uint32_t a) {
    asm volatile("ldmatrix.sync.aligned.m8n8.x2.shared.b16 {%0,%1}, [%2];"
                 : "=r"(r[0]), "=r"(r[1]) : "r"(a));
}
__device__ __forceinline__ void mma16816(float* c, const uint32_t* a, const uint32_t* b) {
    asm volatile(
        "mma.sync.aligned.m16n8k16.row.col.f32.bf16.bf16.f32 "
        "{%0,%1,%2,%3}, {%4,%5,%6,%7}, {%8,%9}, {%0,%1,%2,%3};"
        : "+f"(c[0]), "+f"(c[1]), "+f"(c[2]), "+f"(c[3])
        : "r"(a[0]), "r"(a[1]), "r"(a[2]), "r"(a[3]), "r"(b[0]), "r"(b[1]));
}
__device__ __forceinline__ void cp_async16(uint32_t saddr, const void* gptr) {
    asm volatile("cp.async.cg.shared.global [%0], [%1], 16;" :: "r"(saddr), "l"(gptr));
}
#define CP_COMMIT() asm volatile("cp.async.commit_group;" ::: "memory")
#define CP_WAIT1()  asm volatile("cp.async.wait_group 1;" ::: "memory")
#define CP_WAIT0()  asm volatile("cp.async.wait_group 0;" ::: "memory")

#define TILE_B (128 * 80)
#define STAGE_B (4 * TILE_B)
#define SMEM_MMA (2 * STAGE_B)           // 81920 B (proj/attn)
#define SMEM_SCAN (2 * STAGE_B + 16384)  // 98304 B (+ persistent c tile)

// ---------------- BatchNorm stats: two-phase ----------------
__global__ void bn_stats_part(const float* __restrict__ x) {
    int k = blockIdx.x * blockDim.x + threadIdx.x;
    int z = blockIdx.y;
    float s = 0.f, s2 = 0.f;
    #pragma unroll 8
    for (int b = z * (BB / BNZ); b < (z + 1) * (BB / BNZ); b++) {
        float v = x[(size_t)b * INF + k];
        s += v; s2 += v * v;
    }
    g_bns[z * INF + k] = s;
    g_bns2[z * INF + k] = s2;
}

__global__ void bn_finalize(const float* __restrict__ gamma,
                            const float* __restrict__ beta) {
    int k = blockIdx.x * blockDim.x + threadIdx.x;
    float s = 0.f, s2 = 0.f;
    #pragma unroll
    for (int z = 0; z < BNZ; z++) {
        s += g_bns[z * INF + k];
        s2 += g_bns2[z * INF + k];
    }
    float mean = s * (1.f / BB);
    float var = s2 * (1.f / BB) - mean * mean;
    float sc = gamma[k] * rsqrtf(var + 1e-5f);
    g_scale[k] = sc;
    g_shift[k] = beta[k] - mean * sc;
}

// BN apply fused with bf16 hi/lo split
__global__ void bn_apply_split(const float* __restrict__ x) {
    size_t i = (size_t)blockIdx.x * blockDim.x + threadIdx.x;
    float4 v = ((const float4*)x)[i];
    int k = (int)((i * 4) & (INF - 1));
    float o0 = fmaf(v.x, g_scale[k + 0], g_shift[k + 0]);
    float o1 = fmaf(v.y, g_scale[k + 1], g_shift[k + 1]);
    float o2 = fmaf(v.z, g_scale[k + 2], g_shift[k + 2]);
    float o3 = fmaf(v.w, g_scale[k + 3], g_shift[k + 3]);
    __nv_bfloat16 h0 = __float2bfloat16(o0), h1 = __float2bfloat16(o1);
    __nv_bfloat16 h2 = __float2bfloat16(o2), h3 = __float2bfloat16(o3);
    __nv_bfloat162 ph0; ph0.x = h0; ph0.y = h1;
    __nv_bfloat162 ph1; ph1.x = h2; ph1.y = h3;
    *(__nv_bfloat162*)(g_xnh + i * 4) = ph0;
    *(__nv_bfloat162*)(g_xnh + i * 4 + 2) = ph1;
    __nv_bfloat162 pl0, pl1;
    pl0.x = __float2bfloat16(o0 - __bfloat162float(h0));
    pl0.y = __float2bfloat16(o1 - __bfloat162float(h1));
    pl1.x = __float2bfloat16(o2 - __bfloat162float(h2));
    pl1.y = __float2bfloat16(o3 - __bfloat162float(h3));
    *(__nv_bfloat162*)(g_xnl + i * 4) = pl0;
    *(__nv_bfloat162*)(g_xnl + i * 4 + 2) = pl1;
}

// generic fp32 -> bf16 hi/lo split
__global__ void cvt_split(const float* __restrict__ src,
                          __nv_bfloat16* __restrict__ dh,
                          __nv_bfloat16* __restrict__ dl) {
    size_t i = (size_t)blockIdx.x * blockDim.x + threadIdx.x;
    float4 v = ((const float4*)src)[i];
    __nv_bfloat16 h0 = __float2bfloat16(v.x), h1 = __float2bfloat16(v.y);
    __nv_bfloat16 h2 = __float2bfloat16(v.z), h3 = __float2bfloat16(v.w);
    __nv_bfloat162 ph0; ph0.x = h0; ph0.y = h1;
    __nv_bfloat162 ph1; ph1.x = h2; ph1.y = h3;
    *(__nv_bfloat162*)(dh + i * 4) = ph0;
    *(__nv_bfloat162*)(dh + i * 4 + 2) = ph1;
    __nv_bfloat162 pl0, pl1;
    pl0.x = __float2bfloat16(v.x - __bfloat162float(h0));
    pl0.y = __float2bfloat16(v.y - __bfloat162float(h1));
    pl1.x = __float2bfloat16(v.z - __bfloat162float(h2));
    pl1.y = __float2bfloat16(v.w - __bfloat162float(h3));
    *(__nv_bfloat162*)(dl + i * 4) = pl0;
    *(__nv_bfloat162*)(dl + i * 4 + 2) = pl1;
}

// Blocked permutation (validated) + per-group barrier reset.
__global__ void prep_perm(const float* __restrict__ Whh, const float* __restrict__ Wih,
                          const float* __restrict__ b_ih, const float* __restrict__ b_hh) {
    int r = blockIdx.x;
    if (r == 0 && threadIdx.x < NGRP) g_barv[threadIdx.x * 32] = 0u;
    int t = r >> 7, j = r & 127;
    int orig = (j >> 5) * 256 + t * 32 + (j & 31);
    for (int k = threadIdx.x; k < HH; k += blockDim.x) {
        float v = Whh[(size_t)orig * HH + k];
        __nv_bfloat16 h = __float2bfloat16(v);
        g_whhh[(size_t)r * HH + k] = h;
        g_whhl[(size_t)r * HH + k] = __float2bfloat16(v - __bfloat162float(h));
    }
    for (int k = threadIdx.x; k < DD; k += blockDim.x) {
        float v = Wih[(size_t)orig * DD + k];
        __nv_bfloat16 h = __float2bfloat16(v);
        g_wihh[(size_t)r * DD + k] = h;
        g_wihl[(size_t)r * DD + k] = __float2bfloat16(v - __bfloat162float(h));
    }
    if (threadIdx.x == 0) g_biasp[r] = b_ih[orig] + b_hh[orig];
}

// ============ proj = xn @ W_in^T via mma.sync bf16x3 -> bf16 hi/lo out ============
__global__ void __launch_bounds__(256, 2)
proj_mma() {
    extern __shared__ __align__(128) char sm[];
    const int tid = threadIdx.x;
    const int wid = tid >> 5, lane = tid & 31;
    const int m0 = blockIdx.x * 128;
    const int n0 = blockIdx.y * 128;
    const int wm = (wid >> 2) * 64;
    const int wn = (wid & 3) * 32;
    const uint32_t smu = smem_to_u32(sm);

    const __nv_bfloat16* src0 = g_xnh + (size_t)m0 * INF;
    const __nv_bfloat16* src1 = g_xnl + (size_t)m0 * INF;
    const __nv_bfloat16* src2 = g_wh + (size_t)n0 * INF;
    const __nv_bfloat16* src3 = g_wl + (size_t)n0 * INF;

    float acc[4][4][4];
    #pragma unroll
    for (int i = 0; i < 4; i++)
        #pragma unroll
        for (int j = 0; j < 4; j++)
            #pragma unroll
            for (int f = 0; f < 4; f++) acc[i][j][f] = 0.f;

    const int r0 = tid >> 2, g0 = tid & 3;
    const int r1 = (tid + 256) >> 2;

    auto stage = [&](int st, int k0) {
        uint32_t sb = smu + st * STAGE_B;
        const __nv_bfloat16* s[4] = {src0, src1, src2, src3};
        #pragma unroll
        for (int t = 0; t < 4; t++) {
            cp_async16(sb + t * TILE_B + r0 * 80 + g0 * 16,
                       s[t] + (size_t)r0 * INF + k0 + g0 * 8);
            cp_async16(sb + t * TILE_B + r1 * 80 + g0 * 16,
                       s[t] + (size_t)r1 * INF + k0 + g0 * 8);
        }
        CP_COMMIT();
    };
    auto compute = [&](int st) {
        const uint32_t sAh = smu + st * STAGE_B;
        const uint32_t sAl = sAh + TILE_B;
        const uint32_t sBh = sAh + 2 * TILE_B;
        const uint32_t sBl = sAh + 3 * TILE_B;
        #pragma unroll
        for (int ks = 0; ks < 2; ks++) {
            const int kb = ks * 32;
            uint32_t bh[4][2], bl[4][2];
            const uint32_t boff = (uint32_t)(wn + (lane & 7)) * 80 + kb + ((lane >> 3) & 1) * 16;
            #pragma unroll
            for (int ni = 0; ni < 4; ni++) {
                ldsm_x2(bh[ni], sBh + boff + ni * 8 * 80);
                ldsm_x2(bl[ni], sBl + boff + ni * 8 * 80);
            }
            const uint32_t aoff = (uint32_t)(wm + (lane & 15)) * 80 + kb + (lane >> 4) * 16;
            #pragma unroll
            for (int mi = 0; mi < 4; mi++) {
                uint32_t ah[4], al[4];
                ldsm_x4(ah, sAh + aoff + mi * 16 * 80);
                ldsm_x4(al, sAl + aoff + mi * 16 * 80);
                #pragma unroll
                for (int ni = 0; ni < 4; ni++) {
                    mma16816(acc[mi][ni], ah, bh[ni]);
                    mma16816(acc[mi][ni], ah, bl[ni]);
                    mma16816(acc[mi][ni], al, bh[ni]);
                }
            }
        }
    };

    stage(0, 0);
    int cur = 0;
    #pragma unroll 1
    for (int k0 = 0; k0 < INF; k0 += 32) {
        bool more = (k0 + 32 < INF);
        if (more) stage(cur ^ 1, k0 + 32);
        if (more) CP_WAIT1(); else CP_WAIT0();
        __syncthreads();
        compute(cur);
        __syncthreads();
        cur ^= 1;
    }

    const int gid = lane >> 2, tig = lane & 3;
    #pragma unroll
    for (int mi = 0; mi < 4; mi++) {
        int row0 = m0 + wm + mi * 16 + gid;
        #pragma unroll
        for (int ni = 0; ni < 4; ni++) {
            int col = n0 + wn + ni * 8 + tig * 2;
            const float* a = acc[mi][ni];
            #pragma unroll
            for (int half = 0; half < 2; half++) {
                int row = row0 + half * 8;
                float c0 = a[half * 2 + 0], c1 = a[half * 2 + 1];
                __nv_bfloat162 hp, lp;
                hp.x = __float2bfloat16(c0); hp.y = __float2bfloat16(c1);
                lp.x = __float2bfloat16(c0 - __bfloat162float(hp.x));
                lp.y = __float2bfloat16(c1 - __bfloat162float(hp.y));
                *(__nv_bfloat162*)(g_pjh + (size_t)row * INF + col) = hp;
                *(__nv_bfloat162*)(g_pjl + (size_t)row * INF + col) = lp;
            }
        }
    }
}

// ===== persistent scan (R14 config): per-group barrier, c in persistent smem =====
__device__ __forceinline__ float fsig(float x) {
    return __fdividef(1.f, 1.f + __expf(-x));
}
__device__ __forceinline__ float ftanh(float x) {
    return __fdividef(2.f, 1.f + __expf(-2.f * x)) - 1.f;
}

__global__ void __launch_bounds__(256, 2)
scan_persist() {
    extern __shared__ __align__(128) char sm[];
    const int tid = threadIdx.x;
    const int wid = tid >> 5, lane = tid & 31;
    const int m0 = blockIdx.x * 128;
    const int t = blockIdx.y;          // h-quarter
    const int n0 = t * 128;
    const int wm = (wid >> 2) * 64;
    const int wn = (wid & 3) * 32;
    const uint32_t smu = smem_to_u32(sm);
    const size_t ld1 = (size_t)SS * HH;
    const int r0 = tid >> 2, g0 = tid & 3;
    const int r1 = (tid + 256) >> 2;
    const int gid = lane >> 2, tig = lane & 3;
    unsigned* barp = &g_barv[blockIdx.x * 32];
    float* c_sm = (float*)(sm + 2 * STAGE_B);  // persistent 4096-float c tile

    #pragma unroll 1
    for (int s = 0; s < SS; s++) {
        const int c0 = (s == 0) ? 8 : 0;
        const __nv_bfloat16* a1h = g_hsbh + (size_t)(s - 1) * HH;
        const __nv_bfloat16* a1l = g_hsbl + (size_t)(s - 1) * HH;
        const __nv_bfloat16* a2h = g_pjh + (size_t)s * DD;
        const __nv_bfloat16* a2l = g_pjl + (size_t)s * DD;

        float acc[4][4][4];
        #pragma unroll
        for (int i = 0; i < 4; i++)
            #pragma unroll
            for (int j = 0; j < 4; j++)
                #pragma unroll
                for (int f = 0; f < 4; f++) acc[i][j][f] = 0.f;

        auto stage = [&](int st, int c) {
            const __nv_bfloat16 *pah, *pal, *pbh, *pbl;
            size_t la; int lb, k0;
            if (c < 8) { k0 = c * 32; pah = a1h; pal = a1l; la = ld1;
                         pbh = g_whhh; pbl = g_whhl; lb = HH; }
            else       { k0 = (c - 8) * 32; pah = a2h; pal = a2l; la = INF;
                         pbh = g_wihh; pbl = g_wihl; lb = DD; }
            uint32_t sb = smu + st * STAGE_B;
            cp_async16(sb + r0 * 80 + g0 * 16, pah + (size_t)(m0 + r0) * la + k0 + g0 * 8);
            cp_async16(sb + r1 * 80 + g0 * 16, pah + (size_t)(m0 + r1) * la + k0 + g0 * 8);
            cp_async16(sb + TILE_B + r0 * 80 + g0 * 16, pal + (size_t)(m0 + r0) * la + k0 + g0 * 8);
            cp_async16(sb + TILE_B + r1 * 80 + g0 * 16, pal + (size_t)(m0 + r1) * la + k0 + g0 * 8);
            cp_async16(sb + 2 * TILE_B + r0 * 80 + g0 * 16, pbh + (size_t)(n0 + r0) * lb + k0 + g0 * 8);
            cp_async16(sb + 2 * TILE_B + r1 * 80 + g0 * 16, pbh + (size_t)(n0 + r1) * lb + k0 + g0 * 8);
            cp_async16(sb + 3 * TILE_B + r0 * 80 + g0 * 16, pbl + (size_t)(n0 + r0) * lb + k0 + g0 * 8);
            cp_async16(sb + 3 * TILE_B + r1 * 80 + g0 * 16, pbl + (size_t)(n0 + r1) * lb + k0 + g0 * 8);
            CP_COMMIT();
        };
        auto compute = [&](int st) {
            const uint32_t sAh = smu + st * STAGE_B;
            const uint32_t sAl = sAh + TILE_B;
            const uint32_t sBh = sAh + 2 * TILE_B;
            const uint32_t sBl = sAh + 3 * TILE_B;
            #pragma unroll
            for (int ks = 0; ks < 2; ks++) {
                const int kb = ks * 32;
                uint32_t bh[4][2], bl[4][2];
                const uint32_t boff = (uint32_t)(wn + (lane & 7)) * 80 + kb + ((lane >> 3) & 1) * 16;
                #pragma unroll
                for (int ni = 0; ni < 4; ni++) {
                    ldsm_x2(bh[ni], sBh + boff + ni * 8 * 80);
                    ldsm_x2(bl[ni], sBl + boff + ni * 8 * 80);
                }
                const uint32_t aoff = (uint32_t)(wm + (lane & 15)) * 80 + kb + (lane >> 4) * 16;
                #pragma unroll
                for (int mi = 0; mi < 4; mi++) {
                    uint32_t ah[4], al[4];
                    ldsm_x4(ah, sAh + aoff + mi * 16 * 80);
                    ldsm_x4(al, sAl + aoff + mi * 16 * 80);
                    #pragma unroll
                    for (int ni = 0; ni < 4; ni++) {
                        mma16816(acc[mi][ni], ah, bh[ni]);
                        mma16816(acc[mi][ni], ah, bl[ni]);
                        mma16816(acc[mi][ni], al, bh[ni]);
                    }
                }
            }
        };

        stage(0, c0);
        int cur = 0;
        #pragma unroll 1
        for (int c = c0; c < 10; ++c) {
            bool more = (c < 9);
            if (more) stage(cur ^ 1, c + 1);
            if (more) CP_WAIT1(); else CP_WAIT0();
            __syncthreads();
            compute(cur);
            __syncthreads();
            cur ^= 1;
        }

        // gate exchange via smem (MMA buffers dead; c_sm untouched)
        float* gsm = (float*)sm;       // 128 x 132 fp32
        #pragma unroll
        for (int mi = 0; mi < 4; mi++) {
            int row0 = wm + mi * 16 + gid;
            #pragma unroll
            for (int ni = 0; ni < 4; ni++) {
                int col = wn + ni * 8 + tig * 2;
                const float* a = acc[mi][ni];
                gsm[row0 * 132 + col] = a[0];
                gsm[row0 * 132 + col + 1] = a[1];
                gsm[(row0 + 8) * 132 + col] = a[2];
                gsm[(row0 + 8) * 132 + col + 1] = a[3];
            }
        }
        __syncthreads();

        // fused cell: 4096 cells, 16/thread, MUFU fast math; c in persistent smem
        #pragma unroll
        for (int u = 0; u < 16; u++) {
            int idx = tid + u * 256;
            int row = idx >> 5;
            int hq = idx & 31;
            float gi = gsm[row * 132 + hq]      + g_biasp[t * 128 + hq];
            float gf = gsm[row * 132 + 32 + hq] + g_biasp[t * 128 + 32 + hq];
            float gg = gsm[row * 132 + 64 + hq] + g_biasp[t * 128 + 64 + hq];
            float go = gsm[row * 132 + 96 + hq] + g_biasp[t * 128 + 96 + hq];
            float ig = fsig(gi);
            float fg = fsig(gf);
            float gv = ftanh(gg);
            float og = fsig(go);
            float cp = (s == 0) ? 0.f : c_sm[idx];
            float cn = fmaf(fg, cp, ig * gv);
            c_sm[idx] = cn;
            float hv = og * ftanh(cn);
            int b = m0 + row;
            int h = t * 32 + hq;
            size_t hidx = ((size_t)b * SS + s) * HH + h;
            __nv_bfloat16 hhi = __float2bfloat16(hv);
            g_hsbh[hidx] = hhi;
            g_hsbl[hidx] = __float2bfloat16(hv - __bfloat162float(hhi));
        }
        __syncthreads();

        // per-group barrier: arrive via atomic, poll via plain volatile load
        // (monotone counter; removes reader-side LTS atomic-ALU serialization)
        if (s < SS - 1) {
            if (tid == 0) {
                __threadfence();
                atomicAdd(barp, 1u);
                unsigned target = (unsigned)GRP_CTAS * (unsigned)(s + 1);
                while (*(volatile unsigned*)barp < target) __nanosleep(32);
                __threadfence();
            }
            __syncthreads();
        }
    }
}

// ============ attention logits: split-K bf16x3 MMA -> fp32 partials ============
__global__ void __launch_bounds__(256, 2)
attn_mma() {
    extern __shared__ __align__(128) char sm[];
    const int tid = threadIdx.x;
    const int wid = tid >> 5, lane = tid & 31;
    const int m0 = blockIdx.y * 128;
    const int z = blockIdx.z;
    const int wm = (wid >> 2) * 64;
    const int wn = (wid & 3) * 32;
    const uint32_t smu = smem_to_u32(sm);
    const size_t ldk = (size_t)SS * HH;

    const __nv_bfloat16* src0 = g_hsbh + (size_t)m0 * ldk + z * 4096;
    const __nv_bfloat16* src1 = g_hsbl + (size_t)m0 * ldk + z * 4096;
    const __nv_bfloat16* src2 = g_wtah + z * 4096;
    const __nv_bfloat16* src3 = g_wtal + z * 4096;

    float acc[4][4][4];
    #pragma unroll
    for (int i = 0; i < 4; i++)
        #pragma unroll
        for (int j = 0; j < 4; j++)
            #pragma unroll
            for (int f = 0; f < 4; f++) acc[i][j][f] = 0.f;

    const int r0 = tid >> 2, g0 = tid & 3;
    const int r1 = (tid + 256) >> 2;

    auto stage = [&](int st, int k0) {
        uint32_t sb = smu + st * STAGE_B;
        cp_async16(sb + r0 * 80 + g0 * 16, src0 + (size_t)r0 * ldk + k0 + g0 * 8);
        cp_async16(sb + r1 * 80 + g0 * 16, src0 + (size_t)r1 * ldk + k0 + g0 * 8);
        cp_async16(sb + TILE_B + r0 * 80 + g0 * 16, src1 + (size_t)r0 * ldk + k0 + g0 * 8);
        cp_async16(sb + TILE_B + r1 * 80 + g0 * 16, src1 + (size_t)r1 * ldk + k0 + g0 * 8);
        cp_async16(sb + 2 * TILE_B + r0 * 80 + g0 * 16, src2 + (size_t)r0 * ldk + k0 + g0 * 8);
        cp_async16(sb + 2 * TILE_B + r1 * 80 + g0 * 16, src2 + (size_t)r1 * ldk + k0 + g0 * 8);
        cp_async16(sb + 3 * TILE_B + r0 * 80 + g0 * 16, src3 + (size_t)r0 * ldk + k0 + g0 * 8);
        cp_async16(sb + 3 * TILE_B + r1 * 80 + g0 * 16, src3 + (size_t)r1 * ldk + k0 + g0 * 8);
        CP_COMMIT();
    };
    auto compute = [&](int st) {
        const uint32_t sAh = smu + st * STAGE_B;
        const uint32_t sAl = sAh + TILE_B;
        const uint32_t sBh = sAh + 2 * TILE_B;
        const uint32_t sBl = sAh + 3 * TILE_B;
        #pragma unroll
        for (int ks = 0; ks < 2; ks++) {
            const int kb = ks * 32;
            uint32_t bh[4][2], bl[4][2];
            const uint32_t boff = (uint32_t)(wn + (lane & 7)) * 80 + kb + ((lane >> 3) & 1) * 16;
            #pragma unroll
            for (int ni = 0; ni < 4; ni++) {
                ldsm_x2(bh[ni], sBh + boff + ni * 8 * 80);
                ldsm_x2(bl[ni], sBl + boff + ni * 8 * 80);
            }
            const uint32_t aoff = (uint32_t)(wm + (lane & 15)) * 80 + kb + (lane >> 4) * 16;
            #pragma unroll
            for (int mi = 0; mi < 4; mi++) {
                uint32_t ah[4], al[4];
                ldsm_x4(ah, sAh + aoff + mi * 16 * 80);
                ldsm_x4(al, sAl + aoff + mi * 16 * 80);
                #pragma unroll
                for (int ni = 0; ni < 4; ni++) {
                    mma16816(acc[mi][ni], ah, bh[ni]);
                    mma16816(acc[mi][ni], ah, bl[ni]);
                    mma16816(acc[mi][ni], al, bh[ni]);
                }
            }
        }
    };

    stage(0, 0);
    int cur = 0;
    #pragma unroll 1
    for (int k0 = 0; k0 < 4096; k0 += 32) {
        bool more = (k0 + 32 < 4096);
        if (more) stage(cur ^ 1, k0 + 32);
        if (more) CP_WAIT1(); else CP_WAIT0();
        __syncthreads();
        compute(cur);
        __syncthreads();
        cur ^= 1;
    }

    const int gid = lane >> 2, tig = lane & 3;
    float* outp = g_pattn + (size_t)z * BB * SS;
    #pragma unroll
    for (int mi = 0; mi < 4; mi++) {
        int row0 = m0 + wm + mi * 16 + gid;
        #pragma unroll
        for (int ni = 0; ni < 4; ni++) {
            int col = wn + ni * 8 + tig * 2;
            float2 v0; v0.x = acc[mi][ni][0]; v0.y = acc[mi][ni][1];
            float2 v1; v1.x = acc[mi][ni][2]; v1.y = acc[mi][ni][3];
            *(float2*)(outp + (size_t)row0 * SS + col) = v0;
            *(float2*)(outp + (size_t)(row0 + 8) * SS + col) = v1;
        }
    }
}

// ---------------- attention: reduce split-K partials, relu, softmax ----------------
__global__ void attn_reduce_softmax(const float* __restrict__ b_ta) {
    int b = blockIdx.x;
    int t = threadIdx.x;  // 128
    __shared__ float sh[4];
    float v = 0.f;
    #pragma unroll
    for (int z = 0; z < KSPLIT; z++) v += g_pattn[((size_t)z * BB + b) * SS + t];
    v = fmaxf(v + b_ta[t], 0.f);
    float m = v;
    #pragma unroll
    for (int o = 16; o > 0; o >>= 1) m = fmaxf(m, __shfl_xor_sync(0xffffffffu, m, o));
    if ((t & 31) == 0) sh[t >> 5] = m;
    __syncthreads();
    float m4 = fmaxf(fmaxf(sh[0], sh[1]), fmaxf(sh[2], sh[3]));
    float e = expf(v - m4);
    float ssum = e;
    #pragma unroll
    for (int o = 16; o > 0; o >>= 1) ssum += __shfl_xor_sync(0xffffffffu, ssum, o);
    __syncthreads();
    if ((t & 31) == 0) sh[t >> 5] = ssum;
    __syncthreads();
    float tot = sh[0] + sh[1] + sh[2] + sh[3];
    g_beta[(size_t)b * SS + t] = e / tot;
}

// ---------------- pooled = sum_s beta*hs ; out = pooled @ W_out^T ----------------
__global__ void pool_out(const float* __restrict__ W_out, float* __restrict__ out) {
    int b = blockIdx.x;
    int t = threadIdx.x;  // 256, t == h
    __shared__ float sb[SS];
    __shared__ float red[8];
    if (t < SS) sb[t] = g_beta[(size_t)b * SS + t];
    __syncthreads();
    const __nv_bfloat16* hh = g_hsbh + (size_t)b * SS * HH + t;
    const __nv_bfloat16* hl = g_hsbl + (size_t)b * SS * HH + t;
    float acc = 0.f;
    #pragma unroll 4
    for (int s = 0; s < SS; s++) {
        float hv = __bfloat162float(hh[(size_t)s * HH]) + __bfloat162float(hl[(size_t)s * HH]);
        acc = fmaf(hv, sb[s], acc);
    }
    float v = acc * W_out[t];
    #pragma unroll
    for (int o = 16; o > 0; o >>= 1) v += __shfl_xor_sync(0xffffffffu, v, o);
    if ((t & 31) == 0) red[t >> 5] = v;
    __syncthreads();
    if (t == 0) {
        float r = 0.f;
        #pragma unroll
        for (int w = 0; w < 8; w++) r += red[w];
        out[b] = r;
    }
}

// ---------------- launch ----------------
extern "C" void kernel_launch(void* const* d_in, const int* in_sizes, int n_in,
                              void* d_out, int out_size) {
    const float* x     = (const float*)d_in[0];
    const float* gamma = (const float*)d_in[1];
    const float* beta  = (const float*)d_in[2];
    const float* W_in  = (const float*)d_in[3];
    const float* W_ih  = (const float*)d_in[4];
    const float* b_ih  = (const float*)d_in[5];
    const float* W_hh  = (const float*)d_in[6];
    const float* b_hh  = (const float*)d_in[7];
    const float* W_ta  = (const float*)d_in[8];
    const float* b_ta  = (const float*)d_in[9];
    const float* W_out = (const float*)d_in[10];
    float* out = (float*)d_out;

    __nv_bfloat16 *p_wh, *p_wl, *p_wtah, *p_wtal;
    cudaGetSymbolAddress((void**)&p_wh, g_wh);
    cudaGetSymbolAddress((void**)&p_wl, g_wl);
    cudaGetSymbolAddress((void**)&p_wtah, g_wtah);
    cudaGetSymbolAddress((void**)&p_wtal, g_wtal);

    cudaFuncSetAttribute(proj_mma, cudaFuncAttributeMaxDynamicSharedMemorySize, SMEM_MMA);
    cudaFuncSetAttribute(scan_persist, cudaFuncAttributeMaxDynamicSharedMemorySize, SMEM_SCAN);
    cudaFuncSetAttribute(attn_mma, cudaFuncAttributeMaxDynamicSharedMemorySize, SMEM_MMA);

    // BatchNorm (two-phase) + splits (+ blocked permutation; resets barriers)
    bn_stats_part<<<dim3(INF / 256, BNZ), 256>>>(x);
    bn_finalize<<<INF / 256, 256>>>(gamma, beta);
    bn_apply_split<<<(BB * INF / 4) / 256, 256>>>(x);
    cvt_split<<<((size_t)INF * INF / 4) / 256, 256>>>(W_in, p_wh, p_wl);
    cvt_split<<<((size_t)SS * SS * HH / 4) / 256, 256>>>(W_ta, p_wtah, p_wtal);
    prep_perm<<<H4, 256>>>(W_hh, W_ih, b_ih, b_hh);

    // proj = xn @ W_in^T -> bf16 hi/lo
    proj_mma<<<dim3(BB / 128, INF / 128), 256, SMEM_MMA>>>();

    // LSTM scan: persistent, per-group barriers, smem-resident c
    scan_persist<<<dim3(BB / 128, H4 / 128), 256, SMEM_SCAN>>>();

    // attention: split-K bf16 logits, fused reduce+relu+softmax, pool
    attn_mma<<<dim3(1, BB / 128, KSPLIT), 256, SMEM_MMA>>>();
    attn_reduce_softmax<<<BB, SS>>>(b_ta);
    pool_out<<<BB, HH>>>(W_out, out);
}

// round 17
// speedup vs baseline: 1.0401x; 1.0195x over previous
#include <cuda_runtime.h>
#include <cuda_bf16.h>
#include <math.h>
#include <stdint.h>

#define BB 4096
#define SS 128
#define DD 64
#define HH 256
#define INF 8192
#define H4 1024
#define KSPLIT 8
#define NGRP 32
#define GRP_CTAS 8
#define BNZ 16

// ---------------- scratch (device globals; zero-init at load) ----------------
__device__ float g_scale[INF];
__device__ float g_shift[INF];
__device__ float g_bns[BNZ * INF];
__device__ float g_bns2[BNZ * INF];
__device__ __nv_bfloat16 g_xnh[(size_t)BB * INF];
__device__ __nv_bfloat16 g_xnl[(size_t)BB * INF];
__device__ __nv_bfloat16 g_wh[(size_t)INF * INF];
__device__ __nv_bfloat16 g_wl[(size_t)INF * INF];
__device__ __nv_bfloat16 g_pjh[(size_t)BB * INF];
__device__ __nv_bfloat16 g_pjl[(size_t)BB * INF];
__device__ __nv_bfloat16 g_whhh[(size_t)H4 * HH];        // permuted W_hh hi
__device__ __nv_bfloat16 g_whhl[(size_t)H4 * HH];
__device__ __nv_bfloat16 g_wihh[(size_t)H4 * DD];        // permuted W_ih hi
__device__ __nv_bfloat16 g_wihl[(size_t)H4 * DD];
__device__ float g_biasp[H4];
__device__ __nv_bfloat16 g_wtah[(size_t)SS * SS * HH];
__device__ __nv_bfloat16 g_wtal[(size_t)SS * SS * HH];
__device__ __nv_bfloat16 g_hsbh[(size_t)BB * SS * HH];
__device__ __nv_bfloat16 g_hsbl[(size_t)BB * SS * HH];
__device__ float g_pattn[(size_t)KSPLIT * BB * SS];
__device__ float g_beta[(size_t)BB * SS];
__device__ unsigned g_barv[NGRP * 32];   // per-group barrier counters (padded)

// ============================ PTX helpers (family-wide) ============================
__device__ __forceinline__ uint32_t smem_to_u32(const void* p) {
    uint32_t a;
    asm("{ .reg .u64 t; cvta.to.shared.u64 t, %1; cvt.u32.u64 %0, t; }" : "=r"(a) : "l"(p));
    return a;
}
__device__ __forceinline__ void ldsm_x4(uint32_t* r, uint32_t a) {
    asm volatile("ldmatrix.sync.aligned.m8n8.x4.shared.b16 {%0,%1,%2,%3}, [%4];"
                 : "=r"(r[0]), "=r"(r[1]), "=r"(r[2]), "=r"(r[3]) : "r"(a));
}
__device__ __forceinline__ void mma16816(float* c, const uint32_t* a, const uint32_t* b) {
    asm volatile(
        "mma.sync.aligned.m16n8k16.row.col.f32.bf16.bf16.f32 "
        "{%0,%1,%2,%3}, {%4,%5,%6,%7}, {%8,%9}, {%0,%1,%2,%3};"
        : "+f"(c[0]), "+f"(c[1]), "+f"(c[2]), "+f"(c[3])
        : "r"(a[0]), "r"(a[1]), "r"(a[2]), "r"(a[3]), "r"(b[0]), "r"(b[1]));
}
__device__ __forceinline__ void cp_async16(uint32_t saddr, const void* gptr) {
    asm volatile("cp.async.cg.shared.global [%0], [%1], 16;" :: "r"(saddr), "l"(gptr));
}
#define CP_COMMIT() asm volatile("cp.async.commit_group;" ::: "memory")
#define CP_WAIT1()  asm volatile("cp.async.wait_group 1;" ::: "memory")
#define CP_WAIT0()  asm volatile("cp.async.wait_group 0;" ::: "memory")

#define TILE_B (128 * 80)
#define STAGE_B (4 * TILE_B)
#define SMEM_MMA (2 * STAGE_B)           // 81920 B (proj/attn)
#define SMEM_SCAN (2 * STAGE_B + 16384)  // 98304 B (+ persistent c tile)

// ---------------- BatchNorm stats: two-phase ----------------
__global__ void bn_stats_part(const float* __restrict__ x) {
    int k = blockIdx.x * blockDim.x + threadIdx.x;
    int z = blockIdx.y;
    float s = 0.f, s2 = 0.f;
    #pragma unroll 8
    for (int b = z * (BB / BNZ); b < (z + 1) * (BB / BNZ); b++) {
        float v = x[(size_t)b * INF + k];
        s += v; s2 += v * v;
    }
    g_bns[z * INF + k] = s;
    g_bns2[z * INF + k] = s2;
}

__global__ void bn_finalize(const float* __restrict__ gamma,
                            const float* __restrict__ beta) {
    int k = blockIdx.x * blockDim.x + threadIdx.x;
    float s = 0.f, s2 = 0.f;
    #pragma unroll
    for (int z = 0; z < BNZ; z++) {
        s += g_bns[z * INF + k];
        s2 += g_bns2[z * INF + k];
    }
    float mean = s * (1.f / BB);
    float var = s2 * (1.f / BB) - mean * mean;
    float sc = gamma[k] * rsqrtf(var + 1e-5f);
    g_scale[k] = sc;
    g_shift[k] = beta[k] - mean * sc;
}

// BN apply fused with bf16 hi/lo split
__global__ void bn_apply_split(const float* __restrict__ x) {
    size_t i = (size_t)blockIdx.x * blockDim.x + threadIdx.x;
    float4 v = ((const float4*)x)[i];
    int k = (int)((i * 4) & (INF - 1));
    float o0 = fmaf(v.x, g_scale[k + 0], g_shift[k + 0]);
    float o1 = fmaf(v.y, g_scale[k + 1], g_shift[k + 1]);
    float o2 = fmaf(v.z, g_scale[k + 2], g_shift[k + 2]);
    float o3 = fmaf(v.w, g_scale[k + 3], g_shift[k + 3]);
    __nv_bfloat16 h0 = __float2bfloat16(o0), h1 = __float2bfloat16(o1);
    __nv_bfloat16 h2 = __float2bfloat16(o2), h3 = __float2bfloat16(o3);
    __nv_bfloat162 ph0; ph0.x = h0; ph0.y = h1;
    __nv_bfloat162 ph1; ph1.x = h2; ph1.y = h3;
    *(__nv_bfloat162*)(g_xnh + i * 4) = ph0;
    *(__nv_bfloat162*)(g_xnh + i * 4 + 2) = ph1;
    __nv_bfloat162 pl0, pl1;
    pl0.x = __float2bfloat16(o0 - __bfloat162float(h0));
    pl0.y = __float2bfloat16(o1 - __bfloat162float(h1));
    pl1.x = __float2bfloat16(o2 - __bfloat162float(h2));
    pl1.y = __float2bfloat16(o3 - __bfloat162float(h3));
    *(__nv_bfloat162*)(g_xnl + i * 4) = pl0;
    *(__nv_bfloat162*)(g_xnl + i * 4 + 2) = pl1;
}

// generic fp32 -> bf16 hi/lo split
__global__ void cvt_split(const float* __restrict__ src,
                          __nv_bfloat16* __restrict__ dh,
                          __nv_bfloat16* __restrict__ dl) {
    size_t i = (size_t)blockIdx.x * blockDim.x + threadIdx.x;
    float4 v = ((const float4*)src)[i];
    __nv_bfloat16 h0 = __float2bfloat16(v.x), h1 = __float2bfloat16(v.y);
    __nv_bfloat16 h2 = __float2bfloat16(v.z), h3 = __float2bfloat16(v.w);
    __nv_bfloat162 ph0; ph0.x = h0; ph0.y = h1;
    __nv_bfloat162 ph1; ph1.x = h2; ph1.y = h3;
    *(__nv_bfloat162*)(dh + i * 4) = ph0;
    *(__nv_bfloat162*)(dh + i * 4 + 2) = ph1;
    __nv_bfloat162 pl0, pl1;
    pl0.x = __float2bfloat16(v.x - __bfloat162float(h0));
    pl0.y = __float2bfloat16(v.y - __bfloat162float(h1));
    pl1.x = __float2bfloat16(v.z - __bfloat162float(h2));
    pl1.y = __float2bfloat16(v.w - __bfloat162float(h3));
    *(__nv_bfloat162*)(dl + i * 4) = pl0;
    *(__nv_bfloat162*)(dl + i * 4 + 2) = pl1;
}

// Blocked permutation (validated) + per-group barrier reset.
__global__ void prep_perm(const float* __restrict__ Whh, const float* __restrict__ Wih,
                          const float* __restrict__ b_ih, const float* __restrict__ b_hh) {
    int r = blockIdx.x;
    if (r == 0 && threadIdx.x < NGRP) g_barv[threadIdx.x * 32] = 0u;
    int t = r >> 7, j = r & 127;
    int orig = (j >> 5) * 256 + t * 32 + (j & 31);
    for (int k = threadIdx.x; k < HH; k += blockDim.x) {
        float v = Whh[(size_t)orig * HH + k];
        __nv_bfloat16 h = __float2bfloat16(v);
        g_whhh[(size_t)r * HH + k] = h;
        g_whhl[(size_t)r * HH + k] = __float2bfloat16(v - __bfloat162float(h));
    }
    for (int k = threadIdx.x; k < DD; k += blockDim.x) {
        float v = Wih[(size_t)orig * DD + k];
        __nv_bfloat16 h = __float2bfloat16(v);
        g_wihh[(size_t)r * DD + k] = h;
        g_wihl[(size_t)r * DD + k] = __float2bfloat16(v - __bfloat162float(h));
    }
    if (threadIdx.x == 0) g_biasp[r] = b_ih[orig] + b_hh[orig];
}

// ==== shared MMA compute step: B fragments fetched pairwise via ldsm_x4 ====
// boff4 lanes 0-31: rows wn + ((lane>>4)<<3) + (lane&7), k-half ((lane>>3)&1)*16.
// ldmatrix x4 -> {r0,r1} = frag(ni), {r2,r3} = frag(ni+1).
#define MMA_COMPUTE_BODY(sAh, sAl, sBh, sBl)                                          \
    _Pragma("unroll")                                                                 \
    for (int ks = 0; ks < 2; ks++) {                                                  \
        const int kb = ks * 32;                                                       \
        uint32_t bh[4][2], bl[4][2];                                                  \
        const uint32_t boff4 = (uint32_t)(wn + ((lane >> 4) << 3) + (lane & 7)) * 80  \
                               + kb + (((lane >> 3) & 1) << 4);                       \
        _Pragma("unroll")                                                             \
        for (int nj = 0; nj < 2; nj++) {                                              \
            uint32_t tb[4];                                                           \
            ldsm_x4(tb, (sBh) + boff4 + nj * 16 * 80);                                \
            bh[nj * 2][0] = tb[0]; bh[nj * 2][1] = tb[1];                             \
            bh[nj * 2 + 1][0] = tb[2]; bh[nj * 2 + 1][1] = tb[3];                     \
            ldsm_x4(tb, (sBl) + boff4 + nj * 16 * 80);                                \
            bl[nj * 2][0] = tb[0]; bl[nj * 2][1] = tb[1];                             \
            bl[nj * 2 + 1][0] = tb[2]; bl[nj * 2 + 1][1] = tb[3];                     \
        }                                                                             \
        const uint32_t aoff = (uint32_t)(wm + (lane & 15)) * 80 + kb                  \
                              + (lane >> 4) * 16;                                     \
        _Pragma("unroll")                                                             \
        for (int mi = 0; mi < 4; mi++) {                                              \
            uint32_t ah[4], al[4];                                                    \
            ldsm_x4(ah, (sAh) + aoff + mi * 16 * 80);                                 \
            ldsm_x4(al, (sAl) + aoff + mi * 16 * 80);                                 \
            _Pragma("unroll")                                                         \
            for (int ni = 0; ni < 4; ni++) {                                          \
                mma16816(acc[mi][ni], ah, bh[ni]);                                    \
                mma16816(acc[mi][ni], ah, bl[ni]);                                    \
                mma16816(acc[mi][ni], al, bh[ni]);                                    \
            }                                                                         \
        }                                                                             \
    }

// ============ proj = xn @ W_in^T via mma.sync bf16x3 -> bf16 hi/lo out ============
__global__ void __launch_bounds__(256, 2)
proj_mma() {
    extern __shared__ __align__(128) char sm[];
    const int tid = threadIdx.x;
    const int wid = tid >> 5, lane = tid & 31;
    const int m0 = blockIdx.x * 128;
    const int n0 = blockIdx.y * 128;
    const int wm = (wid >> 2) * 64;
    const int wn = (wid & 3) * 32;
    const uint32_t smu = smem_to_u32(sm);

    const __nv_bfloat16* src0 = g_xnh + (size_t)m0 * INF;
    const __nv_bfloat16* src1 = g_xnl + (size_t)m0 * INF;
    const __nv_bfloat16* src2 = g_wh + (size_t)n0 * INF;
    const __nv_bfloat16* src3 = g_wl + (size_t)n0 * INF;

    float acc[4][4][4];
    #pragma unroll
    for (int i = 0; i < 4; i++)
        #pragma unroll
        for (int j = 0; j < 4; j++)
            #pragma unroll
            for (int f = 0; f < 4; f++) acc[i][j][f] = 0.f;

    const int r0 = tid >> 2, g0 = tid & 3;
    const int r1 = (tid + 256) >> 2;

    auto stage = [&](int st, int k0) {
        uint32_t sb = smu + st * STAGE_B;
        const __nv_bfloat16* s[4] = {src0, src1, src2, src3};
        #pragma unroll
        for (int t = 0; t < 4; t++) {
            cp_async16(sb + t * TILE_B + r0 * 80 + g0 * 16,
                       s[t] + (size_t)r0 * INF + k0 + g0 * 8);
            cp_async16(sb + t * TILE_B + r1 * 80 + g0 * 16,
                       s[t] + (size_t)r1 * INF + k0 + g0 * 8);
        }
        CP_COMMIT();
    };
    auto compute = [&](int st) {
        const uint32_t sAh = smu + st * STAGE_B;
        const uint32_t sAl = sAh + TILE_B;
        const uint32_t sBh = sAh + 2 * TILE_B;
        const uint32_t sBl = sAh + 3 * TILE_B;
        MMA_COMPUTE_BODY(sAh, sAl, sBh, sBl)
    };

    stage(0, 0);
    int cur = 0;
    #pragma unroll 1
    for (int k0 = 0; k0 < INF; k0 += 32) {
        bool more = (k0 + 32 < INF);
        if (more) stage(cur ^ 1, k0 + 32);
        if (more) CP_WAIT1(); else CP_WAIT0();
        __syncthreads();
        compute(cur);
        __syncthreads();
        cur ^= 1;
    }

    const int gid = lane >> 2, tig = lane & 3;
    #pragma unroll
    for (int mi = 0; mi < 4; mi++) {
        int row0 = m0 + wm + mi * 16 + gid;
        #pragma unroll
        for (int ni = 0; ni < 4; ni++) {
            int col = n0 + wn + ni * 8 + tig * 2;
            const float* a = acc[mi][ni];
            #pragma unroll
            for (int half = 0; half < 2; half++) {
                int row = row0 + half * 8;
                float c0 = a[half * 2 + 0], c1 = a[half * 2 + 1];
                __nv_bfloat162 hp, lp;
                hp.x = __float2bfloat16(c0); hp.y = __float2bfloat16(c1);
                lp.x = __float2bfloat16(c0 - __bfloat162float(hp.x));
                lp.y = __float2bfloat16(c1 - __bfloat162float(hp.y));
                *(__nv_bfloat162*)(g_pjh + (size_t)row * INF + col) = hp;
                *(__nv_bfloat162*)(g_pjl + (size_t)row * INF + col) = lp;
            }
        }
    }
}

// ===== persistent scan: per-group barrier, c in persistent smem =====
__device__ __forceinline__ float fsig(float x) {
    return __fdividef(1.f, 1.f + __expf(-x));
}
__device__ __forceinline__ float ftanh(float x) {
    return __fdividef(2.f, 1.f + __expf(-2.f * x)) - 1.f;
}

__global__ void __launch_bounds__(256, 2)
scan_persist() {
    extern __shared__ __align__(128) char sm[];
    const int tid = threadIdx.x;
    const int wid = tid >> 5, lane = tid & 31;
    const int m0 = blockIdx.x * 128;
    const int t = blockIdx.y;          // h-quarter
    const int n0 = t * 128;
    const int wm = (wid >> 2) * 64;
    const int wn = (wid & 3) * 32;
    const uint32_t smu = smem_to_u32(sm);
    const size_t ld1 = (size_t)SS * HH;
    const int r0 = tid >> 2, g0 = tid & 3;
    const int r1 = (tid + 256) >> 2;
    const int gid = lane >> 2, tig = lane & 3;
    unsigned* barp = &g_barv[blockIdx.x * 32];
    float* c_sm = (float*)(sm + 2 * STAGE_B);  // persistent 4096-float c tile

    #pragma unroll 1
    for (int s = 0; s < SS; s++) {
        const int c0 = (s == 0) ? 8 : 0;
        const __nv_bfloat16* a1h = g_hsbh + (size_t)(s - 1) * HH;
        const __nv_bfloat16* a1l = g_hsbl + (size_t)(s - 1) * HH;
        const __nv_bfloat16* a2h = g_pjh + (size_t)s * DD;
        const __nv_bfloat16* a2l = g_pjl + (size_t)s * DD;

        float acc[4][4][4];
        #pragma unroll
        for (int i = 0; i < 4; i++)
            #pragma unroll
            for (int j = 0; j < 4; j++)
                #pragma unroll
                for (int f = 0; f < 4; f++) acc[i][j][f] = 0.f;

        auto stage = [&](int st, int c) {
            const __nv_bfloat16 *pah, *pal, *pbh, *pbl;
            size_t la; int lb, k0;
            if (c < 8) { k0 = c * 32; pah = a1h; pal = a1l; la = ld1;
                         pbh = g_whhh; pbl = g_whhl; lb = HH; }
            else       { k0 = (c - 8) * 32; pah = a2h; pal = a2l; la = INF;
                         pbh = g_wihh; pbl = g_wihl; lb = DD; }
            uint32_t sb = smu + st * STAGE_B;
            cp_async16(sb + r0 * 80 + g0 * 16, pah + (size_t)(m0 + r0) * la + k0 + g0 * 8);
            cp_async16(sb + r1 * 80 + g0 * 16, pah + (size_t)(m0 + r1) * la + k0 + g0 * 8);
            cp_async16(sb + TILE_B + r0 * 80 + g0 * 16, pal + (size_t)(m0 + r0) * la + k0 + g0 * 8);
            cp_async16(sb + TILE_B + r1 * 80 + g0 * 16, pal + (size_t)(m0 + r1) * la + k0 + g0 * 8);
            cp_async16(sb + 2 * TILE_B + r0 * 80 + g0 * 16, pbh + (size_t)(n0 + r0) * lb + k0 + g0 * 8);
            cp_async16(sb + 2 * TILE_B + r1 * 80 + g0 * 16, pbh + (size_t)(n0 + r1) * lb + k0 + g0 * 8);
            cp_async16(sb + 3 * TILE_B + r0 * 80 + g0 * 16, pbl + (size_t)(n0 + r0) * lb + k0 + g0 * 8);
            cp_async16(sb + 3 * TILE_B + r1 * 80 + g0 * 16, pbl + (size_t)(n0 + r1) * lb + k0 + g0 * 8);
            CP_COMMIT();
        };
        auto compute = [&](int st) {
            const uint32_t sAh = smu + st * STAGE_B;
            const uint32_t sAl = sAh + TILE_B;
            const uint32_t sBh = sAh + 2 * TILE_B;
            const uint32_t sBl = sAh + 3 * TILE_B;
            MMA_COMPUTE_BODY(sAh, sAl, sBh, sBl)
        };

        stage(0, c0);
        int cur = 0;
        #pragma unroll 1
        for (int c = c0; c < 10; ++c) {
            bool more = (c < 9);
            if (more) stage(cur ^ 1, c + 1);
            if (more) CP_WAIT1(); else CP_WAIT0();
            __syncthreads();
            compute(cur);
            __syncthreads();
            cur ^= 1;
        }

        // gate exchange via smem (MMA buffers dead; c_sm untouched)
        float* gsm = (float*)sm;       // 128 x 132 fp32
        #pragma unroll
        for (int mi = 0; mi < 4; mi++) {
            int row0 = wm + mi * 16 + gid;
            #pragma unroll
            for (int ni = 0; ni < 4; ni++) {
                int col = wn + ni * 8 + tig * 2;
                const float* a = acc[mi][ni];
                gsm[row0 * 132 + col] = a[0];
                gsm[row0 * 132 + col + 1] = a[1];
                gsm[(row0 + 8) * 132 + col] = a[2];
                gsm[(row0 + 8) * 132 + col + 1] = a[3];
            }
        }
        __syncthreads();

        // fused cell: 4096 cells, 16/thread, MUFU fast math; c in persistent smem
        #pragma unroll
        for (int u = 0; u < 16; u++) {
            int idx = tid + u * 256;
            int row = idx >> 5;
            int hq = idx & 31;
            float gi = gsm[row * 132 + hq]      + g_biasp[t * 128 + hq];
            float gf = gsm[row * 132 + 32 + hq] + g_biasp[t * 128 + 32 + hq];
            float gg = gsm[row * 132 + 64 + hq] + g_biasp[t * 128 + 64 + hq];
            float go = gsm[row * 132 + 96 + hq] + g_biasp[t * 128 + 96 + hq];
            float ig = fsig(gi);
            float fg = fsig(gf);
            float gv = ftanh(gg);
            float og = fsig(go);
            float cp = (s == 0) ? 0.f : c_sm[idx];
            float cn = fmaf(fg, cp, ig * gv);
            c_sm[idx] = cn;
            float hv = og * ftanh(cn);
            int b = m0 + row;
            int h = t * 32 + hq;
            size_t hidx = ((size_t)b * SS + s) * HH + h;
            __nv_bfloat16 hhi = __float2bfloat16(hv);
            g_hsbh[hidx] = hhi;
            g_hsbl[hidx] = __float2bfloat16(hv - __bfloat162float(hhi));
        }
        __syncthreads();

        // per-group barrier: arrive via atomic, poll via plain volatile load
        if (s < SS - 1) {
            if (tid == 0) {
                __threadfence();
                atomicAdd(barp, 1u);
                unsigned target = (unsigned)GRP_CTAS * (unsigned)(s + 1);
                while (*(volatile unsigned*)barp < target) __nanosleep(32);
                __threadfence();
            }
            __syncthreads();
        }
    }
}

// ============ attention logits: split-K bf16x3 MMA -> fp32 partials ============
__global__ void __launch_bounds__(256, 2)
attn_mma() {
    extern __shared__ __align__(128) char sm[];
    const int tid = threadIdx.x;
    const int wid = tid >> 5, lane = tid & 31;
    const int m0 = blockIdx.y * 128;
    const int z = blockIdx.z;
    const int wm = (wid >> 2) * 64;
    const int wn = (wid & 3) * 32;
    const uint32_t smu = smem_to_u32(sm);
    const size_t ldk = (size_t)SS * HH;

    const __nv_bfloat16* src0 = g_hsbh + (size_t)m0 * ldk + z * 4096;
    const __nv_bfloat16* src1 = g_hsbl + (size_t)m0 * ldk + z * 4096;
    const __nv_bfloat16* src2 = g_wtah + z * 4096;
    const __nv_bfloat16* src3 = g_wtal + z * 4096;

    float acc[4][4][4];
    #pragma unroll
    for (int i = 0; i < 4; i++)
        #pragma unroll
        for (int j = 0; j < 4; j++)
            #pragma unroll
            for (int f = 0; f < 4; f++) acc[i][j][f] = 0.f;

    const int r0 = tid >> 2, g0 = tid & 3;
    const int r1 = (tid + 256) >> 2;

    auto stage = [&](int st, int k0) {
        uint32_t sb = smu + st * STAGE_B;
        cp_async16(sb + r0 * 80 + g0 * 16, src0 + (size_t)r0 * ldk + k0 + g0 * 8);
        cp_async16(sb + r1 * 80 + g0 * 16, src0 + (size_t)r1 * ldk + k0 + g0 * 8);
        cp_async16(sb + TILE_B + r0 * 80 + g0 * 16, src1 + (size_t)r0 * ldk + k0 + g0 * 8);
        cp_async16(sb + TILE_B + r1 * 80 + g0 * 16, src1 + (size_t)r1 * ldk + k0 + g0 * 8);
        cp_async16(sb + 2 * TILE_B + r0 * 80 + g0 * 16, src2 + (size_t)r0 * ldk + k0 + g0 * 8);
        cp_async16(sb + 2 * TILE_B + r1 * 80 + g0 * 16, src2 + (size_t)r1 * ldk + k0 + g0 * 8);
        cp_async16(sb + 3 * TILE_B + r0 * 80 + g0 * 16, src3 + (size_t)r0 * ldk + k0 + g0 * 8);
        cp_async16(sb + 3 * TILE_B + r1 * 80 + g0 * 16, src3 + (size_t)r1 * ldk + k0 + g0 * 8);
        CP_COMMIT();
    };
    auto compute = [&](int st) {
        const uint32_t sAh = smu + st * STAGE_B;
        const uint32_t sAl = sAh + TILE_B;
        const uint32_t sBh = sAh + 2 * TILE_B;
        const uint32_t sBl = sAh + 3 * TILE_B;
        MMA_COMPUTE_BODY(sAh, sAl, sBh, sBl)
    };

    stage(0, 0);
    int cur = 0;
    #pragma unroll 1
    for (int k0 = 0; k0 < 4096; k0 += 32) {
        bool more = (k0 + 32 < 4096);
        if (more) stage(cur ^ 1, k0 + 32);
        if (more) CP_WAIT1(); else CP_WAIT0();
        __syncthreads();
        compute(cur);
        __syncthreads();
        cur ^= 1;
    }

    const int gid = lane >> 2, tig = lane & 3;
    float* outp = g_pattn + (size_t)z * BB * SS;
    #pragma unroll
    for (int mi = 0; mi < 4; mi++) {
        int row0 = m0 + wm + mi * 16 + gid;
        #pragma unroll
        for (int ni = 0; ni < 4; ni++) {
            int col = wn + ni * 8 + tig * 2;
            float2 v0; v0.x = acc[mi][ni][0]; v0.y = acc[mi][ni][1];
            float2 v1; v1.x = acc[mi][ni][2]; v1.y = acc[mi][ni][3];
            *(float2*)(outp + (size_t)row0 * SS + col) = v0;
            *(float2*)(outp + (size_t)(row0 + 8) * SS + col) = v1;
        }
    }
}

// ---------------- attention: reduce split-K partials, relu, softmax ----------------
__global__ void attn_reduce_softmax(const float* __restrict__ b_ta) {
    int b = blockIdx.x;
    int t = threadIdx.x;  // 128
    __shared__ float sh[4];
    float v = 0.f;
    #pragma unroll
    for (int z = 0; z < KSPLIT; z++) v += g_pattn[((size_t)z * BB + b) * SS + t];
    v = fmaxf(v + b_ta[t], 0.f);
    float m = v;
    #pragma unroll
    for (int o = 16; o > 0; o >>= 1) m = fmaxf(m, __shfl_xor_sync(0xffffffffu, m, o));
    if ((t & 31) == 0) sh[t >> 5] = m;
    __syncthreads();
    float m4 = fmaxf(fmaxf(sh[0], sh[1]), fmaxf(sh[2], sh[3]));
    float e = expf(v - m4);
    float ssum = e;
    #pragma unroll
    for (int o = 16; o > 0; o >>= 1) ssum += __shfl_xor_sync(0xffffffffu, ssum, o);
    __syncthreads();
    if ((t & 31) == 0) sh[t >> 5] = ssum;
    __syncthreads();
    float tot = sh[0] + sh[1] + sh[2] + sh[3];
    g_beta[(size_t)b * SS + t] = e / tot;
}

// ---------------- pooled = sum_s beta*hs ; out = pooled @ W_out^T ----------------
__global__ void pool_out(const float* __restrict__ W_out, float* __restrict__ out) {
    int b = blockIdx.x;
    int t = threadIdx.x;  // 256, t == h
    __shared__ float sb[SS];
    __shared__ float red[8];
    if (t < SS) sb[t] = g_beta[(size_t)b * SS + t];
    __syncthreads();
    const __nv_bfloat16* hh = g_hsbh + (size_t)b * SS * HH + t;
    const __nv_bfloat16* hl = g_hsbl + (size_t)b * SS * HH + t;
    float acc = 0.f;
    #pragma unroll 4
    for (int s = 0; s < SS; s++) {
        float hv = __bfloat162float(hh[(size_t)s * HH]) + __bfloat162float(hl[(size_t)s * HH]);
        acc = fmaf(hv, sb[s], acc);
    }
    float v = acc * W_out[t];
    #pragma unroll
    for (int o = 16; o > 0; o >>= 1) v += __shfl_xor_sync(0xffffffffu, v, o);
    if ((t & 31) == 0) red[t >> 5] = v;
    __syncthreads();
    if (t == 0) {
        float r = 0.f;
        #pragma unroll
        for (int w = 0; w < 8; w++) r += red[w];
        out[b] = r;
    }
}

// ---------------- launch ----------------
extern "C" void kernel_launch(void* const* d_in, const int* in_sizes, int n_in,
                              void* d_out, int out_size) {
    const float* x     = (const float*)d_in[0];
    const float* gamma = (const float*)d_in[1];
    const float* beta  = (const float*)d_in[2];
    const float* W_in  = (const float*)d_in[3];
    const float* W_ih  = (const float*)d_in[4];
    const float* b_ih  = (const float*)d_in[5];
    const float* W_hh  = (const float*)d_in[6];
    const float* b_hh  = (const float*)d_in[7];
    const float* W_ta  = (const float*)d_in[8];
    const float* b_ta  = (const float*)d_in[9];
    const float* W_out = (const float*)d_in[10];
    float* out = (float*)d_out;

    __nv_bfloat16 *p_wh, *p_wl, *p_wtah, *p_wtal;
    cudaGetSymbolAddress((void**)&p_wh, g_wh);
    cudaGetSymbolAddress((void**)&p_wl, g_wl);
    cudaGetSymbolAddress((void**)&p_wtah, g_wtah);
    cudaGetSymbolAddress((void**)&p_wtal, g_wtal);

    cudaFuncSetAttribute(proj_mma, cudaFuncAttributeMaxDynamicSharedMemorySize, SMEM_MMA);
    cudaFuncSetAttribute(scan_persist, cudaFuncAttributeMaxDynamicSharedMemorySize, SMEM_SCAN);
    cudaFuncSetAttribute(attn_mma, cudaFuncAttributeMaxDynamicSharedMemorySize, SMEM_MMA);

    // BatchNorm (two-phase) + splits (+ blocked permutation; resets barriers)
    bn_stats_part<<<dim3(INF / 256, BNZ), 256>>>(x);
    bn_finalize<<<INF / 256, 256>>>(gamma, beta);
    bn_apply_split<<<(BB * INF / 4) / 256, 256>>>(x);
    cvt_split<<<((size_t)INF * INF / 4) / 256, 256>>>(W_in, p_wh, p_wl);
    cvt_split<<<((size_t)SS * SS * HH / 4) / 256, 256>>>(W_ta, p_wtah, p_wtal);
    prep_perm<<<H4, 256>>>(W_hh, W_ih, b_ih, b_hh);

    // proj = xn @ W_in^T -> bf16 hi/lo
    proj_mma<<<dim3(BB / 128, INF / 128), 256, SMEM_MMA>>>();

    // LSTM scan: persistent, per-group barriers, smem-resident c
    scan_persist<<<dim3(BB / 128, H4 / 128), 256, SMEM_SCAN>>>();

    // attention: split-K bf16 logits, fused reduce+relu+softmax, pool
    attn_mma<<<dim3(1, BB / 128, KSPLIT), 256, SMEM_MMA>>>();
    attn_reduce_softmax<<<BB, SS>>>(b_ta);
    pool_out<<<BB, HH>>>(W_out, out);
}